// round 2
// baseline (speedup 1.0000x reference)
#include <cuda_runtime.h>
#include <math.h>

#define SEQ 1024
#define EMB 256
#define NH  8
#define HD  32

// Scratch (device globals; no allocation allowed)
__device__ float g_q[SEQ*EMB];
__device__ float g_k[SEQ*EMB];
__device__ float g_v[SEQ*EMB];
__device__ float g_rel[SEQ*SEQ];
__device__ float g_ctx[SEQ*EMB];

// ---------------- rel precompute: rel[i][j] = log(|p_i - p_j| + 1) ----------------
__global__ void rel_kernel(const float* __restrict__ pos) {
    int idx = blockIdx.x * 256 + threadIdx.x;      // 1M threads
    int i = idx >> 10, j = idx & 1023;
    float d = fabsf(pos[i] - pos[j]);
    g_rel[idx] = __logf(d + 1.0f);
}

// ---------------- GEMM: C[M x 256] = A[M x 256] @ B[256 x 256]^T (+bias) ----------
// Tile 64x64, BK=32, 256 threads, 4x4 micro-tile, k-major transposed smem,
// float4 compute loads (2 LDS.128 per 16 FMA).
__device__ __forceinline__ void gemm_tile(const float* __restrict__ A,
                                          const float* __restrict__ B,
                                          float* __restrict__ C,
                                          const float* __restrict__ bias,
                                          int m0, int n0) {
    __shared__ float As[32][64];
    __shared__ float Bs[32][64];
    int tid = threadIdx.x;
    int tx = tid & 15, ty = tid >> 4;
    float acc[4][4];
    #pragma unroll
    for (int i = 0; i < 4; i++)
        #pragma unroll
        for (int j = 0; j < 4; j++) acc[i][j] = 0.f;

    for (int k0 = 0; k0 < 256; k0 += 32) {
        #pragma unroll
        for (int t = 0; t < 2; t++) {
            int f = tid + t * 256;
            int kg = f >> 6;         // 0..7
            int m  = f & 63;         // conflict-free STS (bank = m)
            float4 a4 = *(const float4*)(A + (m0 + m) * 256 + k0 + kg * 4);
            As[kg*4+0][m] = a4.x; As[kg*4+1][m] = a4.y;
            As[kg*4+2][m] = a4.z; As[kg*4+3][m] = a4.w;
            float4 b4 = *(const float4*)(B + (n0 + m) * 256 + k0 + kg * 4);
            Bs[kg*4+0][m] = b4.x; Bs[kg*4+1][m] = b4.y;
            Bs[kg*4+2][m] = b4.z; Bs[kg*4+3][m] = b4.w;
        }
        __syncthreads();
        #pragma unroll
        for (int kk = 0; kk < 32; kk++) {
            float4 a4 = *(const float4*)&As[kk][ty * 4];
            float4 b4 = *(const float4*)&Bs[kk][tx * 4];
            float a[4] = {a4.x, a4.y, a4.z, a4.w};
            float b[4] = {b4.x, b4.y, b4.z, b4.w};
            #pragma unroll
            for (int i = 0; i < 4; i++)
                #pragma unroll
                for (int j = 0; j < 4; j++)
                    acc[i][j] += a[i] * b[j];
        }
        __syncthreads();
    }
    #pragma unroll
    for (int i = 0; i < 4; i++) {
        int row = m0 + ty * 4 + i;
        #pragma unroll
        for (int j = 0; j < 4; j++) {
            int col = n0 + tx * 4 + j;
            float v = acc[i][j];
            if (bias) v += bias[col];
            C[row * 256 + col] = v;
        }
    }
}

__global__ void __launch_bounds__(256) proj_kernel(
    const float* __restrict__ Q, const float* __restrict__ K,
    const float* __restrict__ V, const float* __restrict__ Wq,
    const float* __restrict__ Wk, const float* __restrict__ Wv) {
    int z = blockIdx.z;
    const float* A = (z == 0) ? Q : ((z == 1) ? K : V);
    const float* B = (z == 0) ? Wq : ((z == 1) ? Wk : Wv);
    float* Cp      = (z == 0) ? g_q : ((z == 1) ? g_k : g_v);
    gemm_tile(A, B, Cp, nullptr, blockIdx.x * 64, blockIdx.y * 64);
}

__global__ void __launch_bounds__(256) out_kernel(
    const float* __restrict__ Wo, const float* __restrict__ bo,
    float* __restrict__ out) {
    gemm_tile(g_ctx, Wo, out, bo, blockIdx.x * 64, blockIdx.y * 64);
}

// ---------------- Flash attention with relative bias, all heads share g_rel ------
// Grid: (16 q-tiles of 64 rows) x (8 heads). Block = 256 threads = 8 warps.
// Warp w owns 8 q-rows. Per k-chunk (TK=64): lane owns k-cols {lane, lane+32}.
// Accumulator o_i[r] = ctx[row][d=lane], online softmax per row.
__global__ void __launch_bounds__(256) attn_kernel(const float* __restrict__ Wr) {
    __shared__ float qs[64][32];     // q tile [row][d]
    __shared__ float ks[64][36];     // k chunk [j][d] (pad 36 -> 144B rows, 16B aligned)
    __shared__ float vts[32][68];    // v chunk transposed [d][j] (pad 68 -> 272B rows)
    __shared__ float Ps[8][8][64];   // per-warp P broadcast tile

    int h = blockIdx.y;
    int q0 = blockIdx.x * 64;
    int tid = threadIdx.x;
    int w = tid >> 5, lane = tid & 31;
    int hc = h * 32;

    // load q tile (coalesced within 32B groups per row)
    #pragma unroll
    for (int t = 0; t < 2; t++) {
        int f = tid + t * 256;
        int r = f >> 3, dg = f & 7;
        *(float4*)&qs[r][dg * 4] = *(const float4*)(g_q + (q0 + r) * 256 + hc + dg * 4);
    }
    __syncthreads();

    // per-row coeff[h][row] = sum_d q[row][d] * Wr[h*32+d]
    float wrv = Wr[hc + lane];
    float creg[8];
    #pragma unroll
    for (int r = 0; r < 8; r++) {
        float p = qs[w * 8 + r][lane] * wrv;
        #pragma unroll
        for (int s = 16; s > 0; s >>= 1) p += __shfl_xor_sync(0xffffffffu, p, s);
        creg[r] = p;
    }

    float m_i[8], l_i[8], o_i[8];
    #pragma unroll
    for (int r = 0; r < 8; r++) { m_i[r] = -INFINITY; l_i[r] = 0.f; o_i[r] = 0.f; }

    const float scale = 0.0625f;   // 1/sqrt(256)

    for (int k0 = 0; k0 < 1024; k0 += 64) {
        // cooperative load k chunk -> ks[j][d], v chunk -> vts[d][j]
        #pragma unroll
        for (int t = 0; t < 2; t++) {
            int f = tid + t * 256;
            int j = f >> 3, dg = f & 7;
            *(float4*)&ks[j][dg * 4] = *(const float4*)(g_k + (k0 + j) * 256 + hc + dg * 4);
            int jj = f & 63, dgv = f >> 6;   // conflict-free transposed STS (bank = jj)
            float4 v4 = *(const float4*)(g_v + (k0 + jj) * 256 + hc + dgv * 4);
            vts[dgv*4+0][jj] = v4.x; vts[dgv*4+1][jj] = v4.y;
            vts[dgv*4+2][jj] = v4.z; vts[dgv*4+3][jj] = v4.w;
        }
        __syncthreads();

        // S = q.k + coeff*rel  (S0: j=lane, S1: j=lane+32)
        float S0[8], S1[8];
        #pragma unroll
        for (int r = 0; r < 8; r++) {
            const float* relrow = g_rel + (q0 + w * 8 + r) * 1024 + k0;
            S0[r] = creg[r] * relrow[lane];
            S1[r] = creg[r] * relrow[lane + 32];
        }
        #pragma unroll
        for (int d4 = 0; d4 < 32; d4 += 4) {
            float4 k40 = *(const float4*)&ks[lane][d4];
            float4 k41 = *(const float4*)&ks[lane + 32][d4];
            #pragma unroll
            for (int r = 0; r < 8; r++) {
                float4 q4 = *(const float4*)&qs[w * 8 + r][d4];
                S0[r] += q4.x*k40.x + q4.y*k40.y + q4.z*k40.z + q4.w*k40.w;
                S1[r] += q4.x*k41.x + q4.y*k41.y + q4.z*k41.z + q4.w*k41.w;
            }
        }

        // online softmax update per row
        #pragma unroll
        for (int r = 0; r < 8; r++) {
            float s0 = S0[r] * scale, s1 = S1[r] * scale;
            float rm = fmaxf(s0, s1);
            #pragma unroll
            for (int s = 16; s > 0; s >>= 1)
                rm = fmaxf(rm, __shfl_xor_sync(0xffffffffu, rm, s));
            float mn = fmaxf(m_i[r], rm);
            float corr = __expf(m_i[r] - mn);
            float p0 = __expf(s0 - mn);
            float p1 = __expf(s1 - mn);
            float ps = p0 + p1;
            #pragma unroll
            for (int s = 16; s > 0; s >>= 1)
                ps += __shfl_xor_sync(0xffffffffu, ps, s);
            l_i[r] = l_i[r] * corr + ps;
            o_i[r] *= corr;
            m_i[r] = mn;
            Ps[w][r][lane]      = p0;
            Ps[w][r][lane + 32] = p1;
        }
        __syncwarp();

        // o += P @ V  (float4 over j: 9 LDS.128 per 32 FMA)
        #pragma unroll
        for (int j4 = 0; j4 < 64; j4 += 4) {
            float4 v4 = *(const float4*)&vts[lane][j4];
            #pragma unroll
            for (int r = 0; r < 8; r++) {
                float4 p4 = *(const float4*)&Ps[w][r][j4];
                o_i[r] += p4.x*v4.x + p4.y*v4.y + p4.z*v4.z + p4.w*v4.w;
            }
        }
        __syncthreads();
    }

    #pragma unroll
    for (int r = 0; r < 8; r++)
        g_ctx[(q0 + w * 8 + r) * 256 + hc + lane] = o_i[r] / l_i[r];
}

// ---------------- launch ----------------
extern "C" void kernel_launch(void* const* d_in, const int* in_sizes, int n_in,
                              void* d_out, int out_size) {
    const float* V   = (const float*)d_in[0];
    const float* K   = (const float*)d_in[1];
    const float* Q   = (const float*)d_in[2];
    const float* pos = (const float*)d_in[3];
    const float* Wq  = (const float*)d_in[4];
    const float* Wk  = (const float*)d_in[5];
    const float* Wv  = (const float*)d_in[6];
    const float* Wr  = (const float*)d_in[7];
    const float* Wo  = (const float*)d_in[8];
    const float* bo  = (const float*)d_in[9];
    float* out = (float*)d_out;

    rel_kernel<<<SEQ * SEQ / 256, 256>>>(pos);
    proj_kernel<<<dim3(16, 4, 3), 256>>>(Q, K, V, Wq, Wk, Wv);
    attn_kernel<<<dim3(16, 8), 256>>>(Wr);
    out_kernel<<<dim3(16, 4), 256>>>(Wo, bo, out);
}

// round 3
// speedup vs baseline: 1.9989x; 1.9989x over previous
#include <cuda_runtime.h>
#include <math.h>

#define SEQ 1024
#define EMB 256
#define NH  8
#define HD  32

// Scratch (device globals; no allocation allowed)
__device__ float g_q[SEQ*EMB];
__device__ float g_k[SEQ*EMB];
__device__ float g_v[SEQ*EMB];
__device__ float g_ctx[SEQ*EMB];

// ---- tf32 helpers --------------------------------------------------------
__device__ __forceinline__ unsigned tf32r(float x) {
    unsigned r;
    asm("cvt.rna.tf32.f32 %0, %1;" : "=r"(r) : "f"(x));
    return r;
}

// D += A @ B  for m16n8k8 tf32 (A row-major, B col-major), accumulate in place
__device__ __forceinline__ void mma_tf32(float* d, const unsigned* a, const unsigned* b) {
    asm volatile(
        "mma.sync.aligned.m16n8k8.row.col.f32.tf32.tf32.f32 "
        "{%0,%1,%2,%3}, {%4,%5,%6,%7}, {%8,%9}, {%0,%1,%2,%3};\n"
        : "+f"(d[0]), "+f"(d[1]), "+f"(d[2]), "+f"(d[3])
        : "r"(a[0]), "r"(a[1]), "r"(a[2]), "r"(a[3]),
          "r"(b[0]), "r"(b[1]));
}

// ---- GEMM: C[1024x256] = A[1024x256] @ B[256x256]^T (+bias) --------------
// block 128 threads (4 warps), tile M=64 N=32, BK=64.
// Warp grid 2(m) x 2(n); warp tile 32x16 = 2 m-frags x 2 n-frags.
__device__ __forceinline__ void gemm_dev(const float* __restrict__ A,
                                         const float* __restrict__ B,
                                         float* __restrict__ C,
                                         const float* __restrict__ bias) {
    __shared__ unsigned As[64][68];
    __shared__ unsigned Bs[32][68];
    int tid = threadIdx.x;
    int warp = tid >> 5, lane = tid & 31;
    int g = lane >> 2, t = lane & 3;
    int wm = warp >> 1, wn = warp & 1;
    int m0 = blockIdx.x * 64, n0 = blockIdx.y * 32;

    float acc[2][2][4];
    #pragma unroll
    for (int i = 0; i < 2; i++)
        #pragma unroll
        for (int j = 0; j < 2; j++)
            #pragma unroll
            for (int r = 0; r < 4; r++) acc[i][j][r] = 0.f;

    for (int k0 = 0; k0 < 256; k0 += 64) {
        #pragma unroll
        for (int i = 0; i < 8; i++) {                 // A: 64 rows x 16 float4
            int f = tid + i * 128;
            int r = f >> 4, c4 = f & 15;
            float4 a4 = *(const float4*)(A + (m0 + r) * 256 + k0 + c4 * 4);
            As[r][c4*4+0] = tf32r(a4.x); As[r][c4*4+1] = tf32r(a4.y);
            As[r][c4*4+2] = tf32r(a4.z); As[r][c4*4+3] = tf32r(a4.w);
        }
        #pragma unroll
        for (int i = 0; i < 4; i++) {                 // B: 32 rows x 16 float4
            int f = tid + i * 128;
            int r = f >> 4, c4 = f & 15;
            float4 b4 = *(const float4*)(B + (n0 + r) * 256 + k0 + c4 * 4);
            Bs[r][c4*4+0] = tf32r(b4.x); Bs[r][c4*4+1] = tf32r(b4.y);
            Bs[r][c4*4+2] = tf32r(b4.z); Bs[r][c4*4+3] = tf32r(b4.w);
        }
        __syncthreads();

        #pragma unroll
        for (int ks = 0; ks < 8; ks++) {
            unsigned a[2][4], b[2][2];
            #pragma unroll
            for (int am = 0; am < 2; am++) {
                int row = wm * 32 + am * 16;
                a[am][0] = As[row + g    ][ks*8 + t];
                a[am][1] = As[row + g + 8][ks*8 + t];
                a[am][2] = As[row + g    ][ks*8 + t + 4];
                a[am][3] = As[row + g + 8][ks*8 + t + 4];
            }
            #pragma unroll
            for (int bn = 0; bn < 2; bn++) {
                int nr = wn * 16 + bn * 8 + g;
                b[bn][0] = Bs[nr][ks*8 + t];
                b[bn][1] = Bs[nr][ks*8 + t + 4];
            }
            #pragma unroll
            for (int am = 0; am < 2; am++)
                #pragma unroll
                for (int bn = 0; bn < 2; bn++)
                    mma_tf32(acc[am][bn], a[am], b[bn]);
        }
        __syncthreads();
    }

    #pragma unroll
    for (int am = 0; am < 2; am++) {
        #pragma unroll
        for (int bn = 0; bn < 2; bn++) {
            int col = n0 + wn * 16 + bn * 8 + 2 * t;
            float bx = bias ? bias[col] : 0.f;
            float by = bias ? bias[col + 1] : 0.f;
            int r0 = m0 + wm * 32 + am * 16 + g;
            *(float2*)(C + r0 * 256 + col) =
                make_float2(acc[am][bn][0] + bx, acc[am][bn][1] + by);
            *(float2*)(C + (r0 + 8) * 256 + col) =
                make_float2(acc[am][bn][2] + bx, acc[am][bn][3] + by);
        }
    }
}

__global__ void __launch_bounds__(128) proj_kernel(
    const float* __restrict__ Q, const float* __restrict__ K,
    const float* __restrict__ V, const float* __restrict__ Wq,
    const float* __restrict__ Wk, const float* __restrict__ Wv) {
    const float *A, *B; float* C;
    if (blockIdx.z == 0)      { A = Q; B = Wq; C = g_q; }
    else if (blockIdx.z == 1) { A = K; B = Wk; C = g_k; }
    else                      { A = V; B = Wv; C = g_v; }
    gemm_dev(A, B, C, nullptr);
}

__global__ void __launch_bounds__(128) out_kernel(
    const float* __restrict__ Wo, const float* __restrict__ bo,
    float* __restrict__ out) {
    gemm_dev(g_ctx, Wo, out, bo);
}

// ---- Flash attention, tf32 mma, rel-bias computed on the fly -------------
// Grid (16 q-tiles x 8 heads), block 128 = 4 warps, each warp owns 16 q-rows.
// Per chunk TK=64: QK via m16n8k8 (4 k-steps over d=32, 8 n-frags),
// register softmax (rows live in 4-lane quads), P -> smem -> PV mma.
__global__ void __launch_bounds__(128) attn_kernel(
    const float* __restrict__ Wr, const float* __restrict__ pos) {
    __shared__ unsigned qs[64][36];
    __shared__ unsigned ks_s[64][36];
    __shared__ unsigned vs[64][36];
    __shared__ unsigned Ps[64][68];
    __shared__ float coeff_s[64];

    int h = blockIdx.y, q0 = blockIdx.x * 64;
    int tid = threadIdx.x, warp = tid >> 5, lane = tid & 31;
    int g = lane >> 2, t = lane & 3;
    int hc = h * 32;
    const float scale = 0.0625f;   // 1/sqrt(256), folded into q

    // load q tile (scaled, tf32-rounded)
    #pragma unroll
    for (int i = 0; i < 4; i++) {
        int f = tid + i * 128;               // 64 rows x 8 float4
        int r = f >> 3, c4 = f & 7;
        float4 a4 = *(const float4*)(g_q + (q0 + r) * 256 + hc + c4 * 4);
        qs[r][c4*4+0] = tf32r(a4.x * scale); qs[r][c4*4+1] = tf32r(a4.y * scale);
        qs[r][c4*4+2] = tf32r(a4.z * scale); qs[r][c4*4+3] = tf32r(a4.w * scale);
    }
    __syncthreads();

    // coeff[r] = sum_d q_scaled[r][d] * Wr[h*32+d]   (includes 1/16 scale)
    {
        int rr = warp * 16 + (lane >> 1);
        int half = lane & 1;
        float c = 0.f;
        #pragma unroll
        for (int d = 0; d < 16; d++)
            c += __uint_as_float(qs[rr][half * 16 + d]) * Wr[hc + half * 16 + d];
        c += __shfl_xor_sync(0xffffffffu, c, 1);
        if (!half) coeff_s[rr] = c;
    }
    __syncwarp();

    int r0 = warp * 16 + g, r1 = r0 + 8;
    float cf0 = coeff_s[r0], cf1 = coeff_s[r1];
    float pq0 = __ldg(pos + q0 + r0), pq1 = __ldg(pos + q0 + r1);

    // preload Q A-fragments (fixed for whole kernel)
    unsigned qa[4][4];
    #pragma unroll
    for (int ks = 0; ks < 4; ks++) {
        qa[ks][0] = qs[r0][ks*8 + t];
        qa[ks][1] = qs[r1][ks*8 + t];
        qa[ks][2] = qs[r0][ks*8 + t + 4];
        qa[ks][3] = qs[r1][ks*8 + t + 4];
    }

    float m0 = -INFINITY, m1 = -INFINITY, l0 = 0.f, l1 = 0.f;
    float O[4][4];
    #pragma unroll
    for (int nf = 0; nf < 4; nf++)
        #pragma unroll
        for (int r = 0; r < 4; r++) O[nf][r] = 0.f;

    for (int k0 = 0; k0 < 1024; k0 += 64) {
        // stage K, V chunk (tf32-rounded)
        #pragma unroll
        for (int i = 0; i < 4; i++) {
            int f = tid + i * 128;
            int r = f >> 3, c4 = f & 7;
            float4 k4 = *(const float4*)(g_k + (k0 + r) * 256 + hc + c4 * 4);
            ks_s[r][c4*4+0] = tf32r(k4.x); ks_s[r][c4*4+1] = tf32r(k4.y);
            ks_s[r][c4*4+2] = tf32r(k4.z); ks_s[r][c4*4+3] = tf32r(k4.w);
            float4 v4 = *(const float4*)(g_v + (k0 + r) * 256 + hc + c4 * 4);
            vs[r][c4*4+0] = tf32r(v4.x); vs[r][c4*4+1] = tf32r(v4.y);
            vs[r][c4*4+2] = tf32r(v4.z); vs[r][c4*4+3] = tf32r(v4.w);
        }
        __syncthreads();

        // S = q_scaled . k   (8 n-frags of 8 cols each)
        float S[8][4];
        #pragma unroll
        for (int nf = 0; nf < 8; nf++)
            #pragma unroll
            for (int r = 0; r < 4; r++) S[nf][r] = 0.f;
        #pragma unroll
        for (int ks = 0; ks < 4; ks++) {
            #pragma unroll
            for (int nf = 0; nf < 8; nf++) {
                unsigned b[2];
                int nr = nf * 8 + g;
                b[0] = ks_s[nr][ks*8 + t];
                b[1] = ks_s[nr][ks*8 + t + 4];
                mma_tf32(S[nf], qa[ks], b);
            }
        }

        // + coeff * log(|pq - pj| + 1)  (scaled coeff already)
        #pragma unroll
        for (int nf = 0; nf < 8; nf++) {
            float pj0 = __ldg(pos + k0 + nf * 8 + 2 * t);
            float pj1 = __ldg(pos + k0 + nf * 8 + 2 * t + 1);
            S[nf][0] += cf0 * __logf(fabsf(pq0 - pj0) + 1.f);
            S[nf][1] += cf0 * __logf(fabsf(pq0 - pj1) + 1.f);
            S[nf][2] += cf1 * __logf(fabsf(pq1 - pj0) + 1.f);
            S[nf][3] += cf1 * __logf(fabsf(pq1 - pj1) + 1.f);
        }

        // online softmax (rows r0, r1; reduction over 4-lane quad = t)
        float mx0 = -INFINITY, mx1 = -INFINITY;
        #pragma unroll
        for (int nf = 0; nf < 8; nf++) {
            mx0 = fmaxf(mx0, fmaxf(S[nf][0], S[nf][1]));
            mx1 = fmaxf(mx1, fmaxf(S[nf][2], S[nf][3]));
        }
        mx0 = fmaxf(mx0, __shfl_xor_sync(0xffffffffu, mx0, 1));
        mx0 = fmaxf(mx0, __shfl_xor_sync(0xffffffffu, mx0, 2));
        mx1 = fmaxf(mx1, __shfl_xor_sync(0xffffffffu, mx1, 1));
        mx1 = fmaxf(mx1, __shfl_xor_sync(0xffffffffu, mx1, 2));
        float mn0 = fmaxf(m0, mx0), mn1 = fmaxf(m1, mx1);
        float corr0 = __expf(m0 - mn0), corr1 = __expf(m1 - mn1);
        m0 = mn0; m1 = mn1;

        float ps0 = 0.f, ps1 = 0.f;
        #pragma unroll
        for (int nf = 0; nf < 8; nf++) {
            float p00 = __expf(S[nf][0] - mn0);
            float p01 = __expf(S[nf][1] - mn0);
            float p10 = __expf(S[nf][2] - mn1);
            float p11 = __expf(S[nf][3] - mn1);
            ps0 += p00 + p01; ps1 += p10 + p11;
            Ps[r0][nf*8 + 2*t]     = tf32r(p00);
            Ps[r0][nf*8 + 2*t + 1] = tf32r(p01);
            Ps[r1][nf*8 + 2*t]     = tf32r(p10);
            Ps[r1][nf*8 + 2*t + 1] = tf32r(p11);
        }
        ps0 += __shfl_xor_sync(0xffffffffu, ps0, 1);
        ps0 += __shfl_xor_sync(0xffffffffu, ps0, 2);
        ps1 += __shfl_xor_sync(0xffffffffu, ps1, 1);
        ps1 += __shfl_xor_sync(0xffffffffu, ps1, 2);
        l0 = l0 * corr0 + ps0;
        l1 = l1 * corr1 + ps1;
        #pragma unroll
        for (int nf = 0; nf < 4; nf++) {
            O[nf][0] *= corr0; O[nf][1] *= corr0;
            O[nf][2] *= corr1; O[nf][3] *= corr1;
        }
        __syncwarp();   // Ps rows are warp-private; just order STS before LDS

        // O += P @ V   (8 k-steps over 64 j; 4 n-frags over d=32)
        #pragma unroll
        for (int ks = 0; ks < 8; ks++) {
            unsigned pa[4];
            pa[0] = Ps[r0][ks*8 + t];
            pa[1] = Ps[r1][ks*8 + t];
            pa[2] = Ps[r0][ks*8 + t + 4];
            pa[3] = Ps[r1][ks*8 + t + 4];
            #pragma unroll
            for (int nf = 0; nf < 4; nf++) {
                unsigned b[2];
                b[0] = vs[ks*8 + t    ][nf*8 + g];
                b[1] = vs[ks*8 + t + 4][nf*8 + g];
                mma_tf32(O[nf], pa, b);
            }
        }
        __syncthreads();   // all warps done with ks_s/vs before next stage
    }

    float inv0 = 1.f / l0, inv1 = 1.f / l1;
    #pragma unroll
    for (int nf = 0; nf < 4; nf++) {
        int col = hc + nf * 8 + 2 * t;
        *(float2*)(g_ctx + (q0 + r0) * 256 + col) =
            make_float2(O[nf][0] * inv0, O[nf][1] * inv0);
        *(float2*)(g_ctx + (q0 + r1) * 256 + col) =
            make_float2(O[nf][2] * inv1, O[nf][3] * inv1);
    }
}

// ---- launch --------------------------------------------------------------
extern "C" void kernel_launch(void* const* d_in, const int* in_sizes, int n_in,
                              void* d_out, int out_size) {
    const float* V   = (const float*)d_in[0];
    const float* K   = (const float*)d_in[1];
    const float* Q   = (const float*)d_in[2];
    const float* pos = (const float*)d_in[3];
    const float* Wq  = (const float*)d_in[4];
    const float* Wk  = (const float*)d_in[5];
    const float* Wv  = (const float*)d_in[6];
    const float* Wr  = (const float*)d_in[7];
    const float* Wo  = (const float*)d_in[8];
    const float* bo  = (const float*)d_in[9];
    float* out = (float*)d_out;

    proj_kernel<<<dim3(16, 8, 3), 128>>>(Q, K, V, Wq, Wk, Wv);
    attn_kernel<<<dim3(16, 8), 128>>>(Wr, pos);
    out_kernel<<<dim3(16, 8), 128>>>(Wo, bo, out);
}

// round 4
// speedup vs baseline: 2.4188x; 1.2100x over previous
#include <cuda_runtime.h>
#include <math.h>

#define SEQ 1024

// Scratch (device globals; no allocation allowed)
__device__ float g_q[SEQ*256];
__device__ float g_k[SEQ*256];
__device__ float g_v[SEQ*256];
__device__ float g_ctx[SEQ*256];
__device__ float g_rel[SEQ*SEQ];

// ---- helpers -------------------------------------------------------------
__device__ __forceinline__ unsigned tf32r(float x) {
    unsigned r;
    asm("cvt.rna.tf32.f32 %0, %1;" : "=r"(r) : "f"(x));
    return r;
}

__device__ __forceinline__ void mma_tf32(float* d, const unsigned* a, const unsigned* b) {
    asm volatile(
        "mma.sync.aligned.m16n8k8.row.col.f32.tf32.tf32.f32 "
        "{%0,%1,%2,%3}, {%4,%5,%6,%7}, {%8,%9}, {%0,%1,%2,%3};\n"
        : "+f"(d[0]), "+f"(d[1]), "+f"(d[2]), "+f"(d[3])
        : "r"(a[0]), "r"(a[1]), "r"(a[2]), "r"(a[3]),
          "r"(b[0]), "r"(b[1]));
}

__device__ __forceinline__ void cp16(void* dst, const void* src) {
    unsigned d = (unsigned)__cvta_generic_to_shared(dst);
    asm volatile("cp.async.ca.shared.global [%0], [%1], 16;\n" :: "r"(d), "l"(src));
}
#define CP_COMMIT() asm volatile("cp.async.commit_group;\n")
template <int N> __device__ __forceinline__ void cp_wait() {
    asm volatile("cp.async.wait_group %0;\n" :: "n"(N));
}

// ---- rel precompute: rel[i][j] = log(|p_i - p_j| + 1) --------------------
__global__ void __launch_bounds__(256) rel_kernel(const float* __restrict__ pos) {
    int idx = blockIdx.x * 256 + threadIdx.x;   // 256K threads, 4 j each
    int i = idx >> 8;
    int j4 = (idx & 255) * 4;
    float pi = __ldg(pos + i);
    float4 pj = *(const float4*)(pos + j4);
    float4 r;
    r.x = __logf(fabsf(pi - pj.x) + 1.f);
    r.y = __logf(fabsf(pi - pj.y) + 1.f);
    r.z = __logf(fabsf(pi - pj.z) + 1.f);
    r.w = __logf(fabsf(pi - pj.w) + 1.f);
    *(float4*)(g_rel + i * 1024 + j4) = r;
}

// ---- GEMM: C[1024x256] = A[1024x256] @ B[256x256]^T (+bias) --------------
// Tile M=64 N=64 BK=32, 256 threads (8 warps, 2m x 4n), 2-stage cp.async.
__device__ __forceinline__ void gemm_dev(const float* __restrict__ A,
                                         const float* __restrict__ B,
                                         float* __restrict__ C,
                                         const float* __restrict__ bias,
                                         bool round_out) {
    __shared__ __align__(16) float As[2][64][36];
    __shared__ __align__(16) float Bs[2][64][36];
    int tid = threadIdx.x;
    int warp = tid >> 5, lane = tid & 31;
    int g = lane >> 2, t = lane & 3;
    int wm = warp >> 2, wn = warp & 3;
    int m0 = blockIdx.x * 64, n0 = blockIdx.y * 64;

    float acc[2][2][4];
    #pragma unroll
    for (int i = 0; i < 2; i++)
        #pragma unroll
        for (int j = 0; j < 2; j++)
            #pragma unroll
            for (int r = 0; r < 4; r++) acc[i][j][r] = 0.f;

    auto stage = [&](int s, int k0) {
        #pragma unroll
        for (int i2 = 0; i2 < 2; i2++) {
            int f = tid + i2 * 256;
            int r = f >> 3, c4 = f & 7;
            cp16(&As[s][r][c4 * 4], A + (m0 + r) * 256 + k0 + c4 * 4);
            cp16(&Bs[s][r][c4 * 4], B + (n0 + r) * 256 + k0 + c4 * 4);
        }
        CP_COMMIT();
    };

    stage(0, 0);
    for (int ch = 0; ch < 8; ch++) {
        int s = ch & 1;
        if (ch < 7) stage(s ^ 1, (ch + 1) * 32);
        if (ch < 7) cp_wait<1>(); else cp_wait<0>();
        __syncthreads();
        #pragma unroll
        for (int ks = 0; ks < 4; ks++) {
            unsigned a[2][4], b[2][2];
            #pragma unroll
            for (int am = 0; am < 2; am++) {
                int row = wm * 32 + am * 16 + g;
                a[am][0] = tf32r(As[s][row    ][ks*8 + t]);
                a[am][1] = tf32r(As[s][row + 8][ks*8 + t]);
                a[am][2] = tf32r(As[s][row    ][ks*8 + t + 4]);
                a[am][3] = tf32r(As[s][row + 8][ks*8 + t + 4]);
            }
            #pragma unroll
            for (int bn = 0; bn < 2; bn++) {
                int nr = wn * 16 + bn * 8 + g;
                b[bn][0] = tf32r(Bs[s][nr][ks*8 + t]);
                b[bn][1] = tf32r(Bs[s][nr][ks*8 + t + 4]);
            }
            #pragma unroll
            for (int am = 0; am < 2; am++)
                #pragma unroll
                for (int bn = 0; bn < 2; bn++)
                    mma_tf32(acc[am][bn], a[am], b[bn]);
        }
        __syncthreads();
    }

    #pragma unroll
    for (int am = 0; am < 2; am++) {
        #pragma unroll
        for (int bn = 0; bn < 2; bn++) {
            int col = n0 + wn * 16 + bn * 8 + 2 * t;
            float bx = bias ? bias[col] : 0.f;
            float by = bias ? bias[col + 1] : 0.f;
            int r0 = m0 + wm * 32 + am * 16 + g;
            float v0 = acc[am][bn][0] + bx, v1 = acc[am][bn][1] + by;
            float v2 = acc[am][bn][2] + bx, v3 = acc[am][bn][3] + by;
            if (round_out) {   // pre-round to tf32 so attn feeds raw bits to MMA
                v0 = __uint_as_float(tf32r(v0)); v1 = __uint_as_float(tf32r(v1));
                v2 = __uint_as_float(tf32r(v2)); v3 = __uint_as_float(tf32r(v3));
            }
            *(float2*)(C + r0 * 256 + col)       = make_float2(v0, v1);
            *(float2*)(C + (r0 + 8) * 256 + col) = make_float2(v2, v3);
        }
    }
}

__global__ void __launch_bounds__(256) proj_kernel(
    const float* __restrict__ Q, const float* __restrict__ K,
    const float* __restrict__ V, const float* __restrict__ Wq,
    const float* __restrict__ Wk, const float* __restrict__ Wv) {
    const float *A, *B; float* C;
    if (blockIdx.z == 0)      { A = Q; B = Wq; C = g_q; }
    else if (blockIdx.z == 1) { A = K; B = Wk; C = g_k; }
    else                      { A = V; B = Wv; C = g_v; }
    gemm_dev(A, B, C, nullptr, true);
}

__global__ void __launch_bounds__(256) out_kernel(
    const float* __restrict__ Wo, const float* __restrict__ bo,
    float* __restrict__ out) {
    gemm_dev(g_ctx, Wo, out, bo, false);
}

// ---- Flash attention: tf32 mma, precomputed rel, cp.async pipelines ------
// Grid (16 q-tiles x 8 heads), block 128 = 4 warps x 16 q-rows.
// K double-buffered; V single-buffer prefetched one chunk ahead.
__global__ void __launch_bounds__(128) attn_kernel(const float* __restrict__ Wr) {
    __shared__ __align__(16) float Ks[2][64][36];
    __shared__ __align__(16) float Vs[64][36];
    __shared__ __align__(16) unsigned PsQ[64][68];   // prologue: q staging (stride 36); mainloop: P tile (stride 68)
    __shared__ float coeff_s[64];

    int h = blockIdx.y, q0 = blockIdx.x * 64;
    int tid = threadIdx.x, warp = tid >> 5, lane = tid & 31;
    int g = lane >> 2, t = lane & 3;
    int hc = h * 32;
    const float scale = 0.0625f;   // 1/sqrt(256); exact on tf32 values
    unsigned* qbuf = &PsQ[0][0];   // q view, stride 36

    // load q tile (already tf32-rounded by proj), fold in scale
    #pragma unroll
    for (int i = 0; i < 4; i++) {
        int f = tid + i * 128;
        int r = f >> 3, c4 = f & 7;
        float4 a4 = *(const float4*)(g_q + (q0 + r) * 256 + hc + c4 * 4);
        qbuf[r*36 + c4*4+0] = __float_as_uint(a4.x * scale);
        qbuf[r*36 + c4*4+1] = __float_as_uint(a4.y * scale);
        qbuf[r*36 + c4*4+2] = __float_as_uint(a4.z * scale);
        qbuf[r*36 + c4*4+3] = __float_as_uint(a4.w * scale);
    }
    __syncthreads();

    // coeff[r] = sum_d q_scaled[r][d] * Wr[h*32+d]  (warp-private rows)
    {
        int rr = warp * 16 + (lane >> 1);
        int half = lane & 1;
        float c = 0.f;
        #pragma unroll
        for (int d = 0; d < 16; d++)
            c += __uint_as_float(qbuf[rr*36 + half*16 + d]) * Wr[hc + half*16 + d];
        c += __shfl_xor_sync(0xffffffffu, c, 1);
        if (!half) coeff_s[rr] = c;
    }
    __syncwarp();

    int r0 = warp * 16 + g, r1 = r0 + 8;
    float cf0 = coeff_s[r0], cf1 = coeff_s[r1];
    const float* relp0 = g_rel + (q0 + r0) * 1024;
    const float* relp1 = g_rel + (q0 + r1) * 1024;

    // preload Q fragments (fixed for whole kernel); qbuf dead afterwards
    unsigned qa[4][4];
    #pragma unroll
    for (int ks = 0; ks < 4; ks++) {
        qa[ks][0] = qbuf[r0*36 + ks*8 + t];
        qa[ks][1] = qbuf[r1*36 + ks*8 + t];
        qa[ks][2] = qbuf[r0*36 + ks*8 + t + 4];
        qa[ks][3] = qbuf[r1*36 + ks*8 + t + 4];
    }

    auto stageK = [&](int s, int k0) {
        #pragma unroll
        for (int i = 0; i < 4; i++) {
            int f = tid + i * 128;
            int r = f >> 3, c4 = f & 7;
            cp16(&Ks[s][r][c4 * 4], g_k + (k0 + r) * 256 + hc + c4 * 4);
        }
        CP_COMMIT();
    };
    auto stageV = [&](int k0) {
        #pragma unroll
        for (int i = 0; i < 4; i++) {
            int f = tid + i * 128;
            int r = f >> 3, c4 = f & 7;
            cp16(&Vs[r][c4 * 4], g_v + (k0 + r) * 256 + hc + c4 * 4);
        }
        CP_COMMIT();
    };

    float m0 = -INFINITY, m1 = -INFINITY, l0 = 0.f, l1 = 0.f;
    float O[4][4];
    #pragma unroll
    for (int nf = 0; nf < 4; nf++)
        #pragma unroll
        for (int r = 0; r < 4; r++) O[nf][r] = 0.f;

    stageK(0, 0);
    stageV(0);

    for (int ch = 0; ch < 16; ch++) {
        int s = ch & 1;
        int k0 = ch * 64;
        // outstanding groups: [K(ch), V(ch)] -> wait K(ch)
        cp_wait<1>();
        __syncthreads();                 // K stage s ready; prev chunk fully done
        if (ch < 15) stageK(s ^ 1, k0 + 64);

        // issue rel-bias loads early (L2 hits hide under MMAs)
        float2 rb0[8], rb1[8];
        #pragma unroll
        for (int nf = 0; nf < 8; nf++) {
            rb0[nf] = *(const float2*)(relp0 + k0 + nf*8 + 2*t);
            rb1[nf] = *(const float2*)(relp1 + k0 + nf*8 + 2*t);
        }

        // S = q_scaled . k
        float S[8][4];
        #pragma unroll
        for (int nf = 0; nf < 8; nf++)
            #pragma unroll
            for (int r = 0; r < 4; r++) S[nf][r] = 0.f;
        #pragma unroll
        for (int ks = 0; ks < 4; ks++) {
            #pragma unroll
            for (int nf = 0; nf < 8; nf++) {
                unsigned b[2];
                int nr = nf * 8 + g;
                b[0] = __float_as_uint(Ks[s][nr][ks*8 + t]);
                b[1] = __float_as_uint(Ks[s][nr][ks*8 + t + 4]);
                mma_tf32(S[nf], qa[ks], b);
            }
        }

        // + coeff * rel
        #pragma unroll
        for (int nf = 0; nf < 8; nf++) {
            S[nf][0] += cf0 * rb0[nf].x;
            S[nf][1] += cf0 * rb0[nf].y;
            S[nf][2] += cf1 * rb1[nf].x;
            S[nf][3] += cf1 * rb1[nf].y;
        }

        // online softmax (rows r0, r1; quad reduce over t)
        float mx0 = -INFINITY, mx1 = -INFINITY;
        #pragma unroll
        for (int nf = 0; nf < 8; nf++) {
            mx0 = fmaxf(mx0, fmaxf(S[nf][0], S[nf][1]));
            mx1 = fmaxf(mx1, fmaxf(S[nf][2], S[nf][3]));
        }
        mx0 = fmaxf(mx0, __shfl_xor_sync(0xffffffffu, mx0, 1));
        mx0 = fmaxf(mx0, __shfl_xor_sync(0xffffffffu, mx0, 2));
        mx1 = fmaxf(mx1, __shfl_xor_sync(0xffffffffu, mx1, 1));
        mx1 = fmaxf(mx1, __shfl_xor_sync(0xffffffffu, mx1, 2));
        float mn0 = fmaxf(m0, mx0), mn1 = fmaxf(m1, mx1);
        float corr0 = __expf(m0 - mn0), corr1 = __expf(m1 - mn1);
        m0 = mn0; m1 = mn1;

        float ps0 = 0.f, ps1 = 0.f;
        #pragma unroll
        for (int nf = 0; nf < 8; nf++) {
            float p00 = __expf(S[nf][0] - mn0);
            float p01 = __expf(S[nf][1] - mn0);
            float p10 = __expf(S[nf][2] - mn1);
            float p11 = __expf(S[nf][3] - mn1);
            ps0 += p00 + p01; ps1 += p10 + p11;
            PsQ[r0][nf*8 + 2*t]     = tf32r(p00);
            PsQ[r0][nf*8 + 2*t + 1] = tf32r(p01);
            PsQ[r1][nf*8 + 2*t]     = tf32r(p10);
            PsQ[r1][nf*8 + 2*t + 1] = tf32r(p11);
        }
        ps0 += __shfl_xor_sync(0xffffffffu, ps0, 1);
        ps0 += __shfl_xor_sync(0xffffffffu, ps0, 2);
        ps1 += __shfl_xor_sync(0xffffffffu, ps1, 1);
        ps1 += __shfl_xor_sync(0xffffffffu, ps1, 2);
        l0 = l0 * corr0 + ps0;
        l1 = l1 * corr1 + ps1;
        #pragma unroll
        for (int nf = 0; nf < 4; nf++) {
            O[nf][0] *= corr0; O[nf][1] *= corr0;
            O[nf][2] *= corr1; O[nf][3] *= corr1;
        }
        __syncwarp();   // order Ps STS before LDS (rows warp-private)

        // wait V(ch): outstanding [V(ch), K(ch+1)] (or [V(15)] on last)
        if (ch < 15) cp_wait<1>(); else cp_wait<0>();
        __syncthreads();

        // O += P @ V
        #pragma unroll
        for (int ks = 0; ks < 8; ks++) {
            unsigned pa[4];
            pa[0] = PsQ[r0][ks*8 + t];
            pa[1] = PsQ[r1][ks*8 + t];
            pa[2] = PsQ[r0][ks*8 + t + 4];
            pa[3] = PsQ[r1][ks*8 + t + 4];
            #pragma unroll
            for (int nf = 0; nf < 4; nf++) {
                unsigned b[2];
                b[0] = __float_as_uint(Vs[ks*8 + t    ][nf*8 + g]);
                b[1] = __float_as_uint(Vs[ks*8 + t + 4][nf*8 + g]);
                mma_tf32(O[nf], pa, b);
            }
        }
        __syncthreads();               // all warps done reading Vs
        if (ch < 15) stageV(k0 + 64);  // prefetch next V (consumed after next QK)
    }

    float inv0 = 1.f / l0, inv1 = 1.f / l1;
    #pragma unroll
    for (int nf = 0; nf < 4; nf++) {
        int col = hc + nf * 8 + 2 * t;
        *(float2*)(g_ctx + (q0 + r0) * 256 + col) =
            make_float2(O[nf][0] * inv0, O[nf][1] * inv0);
        *(float2*)(g_ctx + (q0 + r1) * 256 + col) =
            make_float2(O[nf][2] * inv1, O[nf][3] * inv1);
    }
}

// ---- launch --------------------------------------------------------------
extern "C" void kernel_launch(void* const* d_in, const int* in_sizes, int n_in,
                              void* d_out, int out_size) {
    const float* V   = (const float*)d_in[0];
    const float* K   = (const float*)d_in[1];
    const float* Q   = (const float*)d_in[2];
    const float* pos = (const float*)d_in[3];
    const float* Wq  = (const float*)d_in[4];
    const float* Wk  = (const float*)d_in[5];
    const float* Wv  = (const float*)d_in[6];
    const float* Wr  = (const float*)d_in[7];
    const float* Wo  = (const float*)d_in[8];
    const float* bo  = (const float*)d_in[9];
    float* out = (float*)d_out;

    rel_kernel<<<1024, 256>>>(pos);
    proj_kernel<<<dim3(16, 4, 3), 256>>>(Q, K, V, Wq, Wk, Wv);
    attn_kernel<<<dim3(16, 8), 128>>>(Wr);
    out_kernel<<<dim3(16, 4), 256>>>(Wo, bo, out);
}

// round 5
// speedup vs baseline: 2.7227x; 1.1257x over previous
#include <cuda_runtime.h>
#include <math.h>

#define SEQ 1024

// Scratch (device globals; no allocation allowed)
__device__ float g_q[SEQ*256];
__device__ float g_k[SEQ*256];
__device__ float g_v[SEQ*256];
__device__ float g_ctx[SEQ*256];
__device__ float g_rel[SEQ*SEQ];

// ---- helpers -------------------------------------------------------------
__device__ __forceinline__ unsigned tf32r(float x) {
    unsigned r;
    asm("cvt.rna.tf32.f32 %0, %1;" : "=r"(r) : "f"(x));
    return r;
}

__device__ __forceinline__ void mma_tf32(float* d, const unsigned* a, const unsigned* b) {
    asm volatile(
        "mma.sync.aligned.m16n8k8.row.col.f32.tf32.tf32.f32 "
        "{%0,%1,%2,%3}, {%4,%5,%6,%7}, {%8,%9}, {%0,%1,%2,%3};\n"
        : "+f"(d[0]), "+f"(d[1]), "+f"(d[2]), "+f"(d[3])
        : "r"(a[0]), "r"(a[1]), "r"(a[2]), "r"(a[3]),
          "r"(b[0]), "r"(b[1]));
}

__device__ __forceinline__ void cp16(void* dst, const void* src) {
    unsigned d = (unsigned)__cvta_generic_to_shared(dst);
    asm volatile("cp.async.ca.shared.global [%0], [%1], 16;\n" :: "r"(d), "l"(src));
}
#define CP_COMMIT() asm volatile("cp.async.commit_group;\n")
template <int N> __device__ __forceinline__ void cp_wait() {
    asm volatile("cp.async.wait_group %0;\n" :: "n"(N));
}

// ---- GEMM tile: C[32x64] = A[32x256] @ B[64x256]^T (+bias), 128 threads --
// BK=32, 2-stage cp.async. 4 warps, warp tile 32m x 16n (2 m-frags x 2 n-frags).
__device__ __forceinline__ void gemm_dev(const float* __restrict__ A,
                                         const float* __restrict__ B,
                                         float* __restrict__ C,
                                         const float* __restrict__ bias,
                                         bool round_out,
                                         int m0, int n0) {
    __shared__ __align__(16) float As[2][32][36];
    __shared__ __align__(16) float Bs[2][64][36];
    int tid = threadIdx.x;
    int warp = tid >> 5, lane = tid & 31;
    int g = lane >> 2, t = lane & 3;
    int wn = warp;

    float acc[2][2][4];
    #pragma unroll
    for (int i = 0; i < 2; i++)
        #pragma unroll
        for (int j = 0; j < 2; j++)
            #pragma unroll
            for (int r = 0; r < 4; r++) acc[i][j][r] = 0.f;

    auto stage = [&](int s, int k0) {
        #pragma unroll
        for (int i2 = 0; i2 < 2; i2++) {       // A: 32 rows x 8 f4 = 256
            int f = tid + i2 * 128;
            int r = f >> 3, c4 = f & 7;
            cp16(&As[s][r][c4 * 4], A + (m0 + r) * 256 + k0 + c4 * 4);
        }
        #pragma unroll
        for (int i2 = 0; i2 < 4; i2++) {       // B: 64 rows x 8 f4 = 512
            int f = tid + i2 * 128;
            int r = f >> 3, c4 = f & 7;
            cp16(&Bs[s][r][c4 * 4], B + (n0 + r) * 256 + k0 + c4 * 4);
        }
        CP_COMMIT();
    };

    stage(0, 0);
    for (int ch = 0; ch < 8; ch++) {
        int s = ch & 1;
        if (ch < 7) stage(s ^ 1, (ch + 1) * 32);
        if (ch < 7) cp_wait<1>(); else cp_wait<0>();
        __syncthreads();
        #pragma unroll
        for (int ks = 0; ks < 4; ks++) {
            unsigned a[2][4], b[2][2];
            #pragma unroll
            for (int am = 0; am < 2; am++) {
                int row = am * 16 + g;
                a[am][0] = tf32r(As[s][row    ][ks*8 + t]);
                a[am][1] = tf32r(As[s][row + 8][ks*8 + t]);
                a[am][2] = tf32r(As[s][row    ][ks*8 + t + 4]);
                a[am][3] = tf32r(As[s][row + 8][ks*8 + t + 4]);
            }
            #pragma unroll
            for (int bn = 0; bn < 2; bn++) {
                int nr = wn * 16 + bn * 8 + g;
                b[bn][0] = tf32r(Bs[s][nr][ks*8 + t]);
                b[bn][1] = tf32r(Bs[s][nr][ks*8 + t + 4]);
            }
            #pragma unroll
            for (int am = 0; am < 2; am++)
                #pragma unroll
                for (int bn = 0; bn < 2; bn++)
                    mma_tf32(acc[am][bn], a[am], b[bn]);
        }
        __syncthreads();
    }

    #pragma unroll
    for (int am = 0; am < 2; am++) {
        #pragma unroll
        for (int bn = 0; bn < 2; bn++) {
            int col = n0 + wn * 16 + bn * 8 + 2 * t;
            float bx = bias ? bias[col] : 0.f;
            float by = bias ? bias[col + 1] : 0.f;
            int r0 = m0 + am * 16 + g;
            float v0 = acc[am][bn][0] + bx, v1 = acc[am][bn][1] + by;
            float v2 = acc[am][bn][2] + bx, v3 = acc[am][bn][3] + by;
            if (round_out) {
                v0 = __uint_as_float(tf32r(v0)); v1 = __uint_as_float(tf32r(v1));
                v2 = __uint_as_float(tf32r(v2)); v3 = __uint_as_float(tf32r(v3));
            }
            *(float2*)(C + r0 * 256 + col)       = make_float2(v0, v1);
            *(float2*)(C + (r0 + 8) * 256 + col) = make_float2(v2, v3);
        }
    }
}

// ---- prep: z<3 = projections, z==3 = rel precompute ----------------------
__global__ void __launch_bounds__(128) prep_kernel(
    const float* __restrict__ Q, const float* __restrict__ K,
    const float* __restrict__ V, const float* __restrict__ Wq,
    const float* __restrict__ Wk, const float* __restrict__ Wv,
    const float* __restrict__ pos) {
    int z = blockIdx.z;
    if (z < 3) {
        const float *A, *B; float* C;
        if (z == 0)      { A = Q; B = Wq; C = g_q; }
        else if (z == 1) { A = K; B = Wk; C = g_k; }
        else             { A = V; B = Wv; C = g_v; }
        gemm_dev(A, B, C, nullptr, true, blockIdx.x * 32, blockIdx.y * 64);
    } else {
        // rel[i][j] = log(|p_i - p_j| + 1); 128 blocks x 8 rows each
        int bid = blockIdx.y * 32 + blockIdx.x;          // 0..127
        int tid = threadIdx.x;
        int i = bid * 8 + (tid >> 4);
        int jb = (tid & 15) * 64;
        float pi = __ldg(pos + i);
        #pragma unroll
        for (int jj = 0; jj < 16; jj++) {
            int j4 = jb + jj * 4;
            float4 pj = *(const float4*)(pos + j4);
            float4 r;
            r.x = __logf(fabsf(pi - pj.x) + 1.f);
            r.y = __logf(fabsf(pi - pj.y) + 1.f);
            r.z = __logf(fabsf(pi - pj.z) + 1.f);
            r.w = __logf(fabsf(pi - pj.w) + 1.f);
            *(float4*)(g_rel + i * 1024 + j4) = r;
        }
    }
}

__global__ void __launch_bounds__(128) out_kernel(
    const float* __restrict__ Wo, const float* __restrict__ bo,
    float* __restrict__ out) {
    gemm_dev(g_ctx, Wo, out, bo, false, blockIdx.x * 32, blockIdx.y * 64);
}

// ---- Flash attention: warpgroup-split over KV ----------------------------
// Grid (16 q-tiles x 8 heads), block 256 = 2 warpgroups of 4 warps.
// wg0: chunks 0-7 (k 0-511), wg1: chunks 8-15 (k 512-1023); private smem +
// named barriers keep them fully decoupled; (m,l,O) merged at the end.
#define BARW() asm volatile("bar.sync %0, 128;" :: "r"(wg + 1))

__global__ void __launch_bounds__(256) attn_kernel(const float* __restrict__ Wr) {
    extern __shared__ __align__(16) char sm[];
    float*    Ksb   = (float*)sm;                    // [wg][2][64][36]
    float*    Vsb   = (float*)(sm + 36864);          // [wg][64][36]
    unsigned* Psb   = (unsigned*)(sm + 55296);       // [wg][64][68]
    float*    coeff = (float*)(sm + 90112);          // [wg][64]

    int h = blockIdx.y, q0 = blockIdx.x * 64;
    int tid = threadIdx.x, warp = tid >> 5, lane = tid & 31;
    int wg = warp >> 2, wi = warp & 3;
    int wtid = tid & 127;
    int g = lane >> 2, t = lane & 3;
    int hc = h * 32;
    const float scale = 0.0625f;

    float*    myK = Ksb + wg * 2 * 64 * 36;
    float*    myV = Vsb + wg * 64 * 36;
    unsigned* myP = Psb + wg * 64 * 68;
    unsigned* qbuf = myP;                            // q staging alias, stride 36
    float*    myC = coeff + wg * 64;

    // load q tile (tf32-pre-rounded by prep), fold in scale
    #pragma unroll
    for (int i = 0; i < 4; i++) {
        int f = wtid + i * 128;
        int r = f >> 3, c4 = f & 7;
        float4 a4 = *(const float4*)(g_q + (q0 + r) * 256 + hc + c4 * 4);
        qbuf[r*36 + c4*4+0] = __float_as_uint(a4.x * scale);
        qbuf[r*36 + c4*4+1] = __float_as_uint(a4.y * scale);
        qbuf[r*36 + c4*4+2] = __float_as_uint(a4.z * scale);
        qbuf[r*36 + c4*4+3] = __float_as_uint(a4.w * scale);
    }
    BARW();

    // coeff[r] = sum_d q_scaled[r][d] * Wr[h*32+d]  (rows owned by this warp)
    {
        int rr = wi * 16 + (lane >> 1);
        int half = lane & 1;
        float c = 0.f;
        #pragma unroll
        for (int d = 0; d < 16; d++)
            c += __uint_as_float(qbuf[rr*36 + half*16 + d]) * Wr[hc + half*16 + d];
        c += __shfl_xor_sync(0xffffffffu, c, 1);
        if (!half) myC[rr] = c;
    }
    __syncwarp();

    int r0 = wi * 16 + g, r1 = r0 + 8;
    float cf0 = myC[r0], cf1 = myC[r1];
    const float* relp0 = g_rel + (q0 + r0) * 1024;
    const float* relp1 = g_rel + (q0 + r1) * 1024;

    unsigned qa[4][4];
    #pragma unroll
    for (int ks = 0; ks < 4; ks++) {
        qa[ks][0] = qbuf[r0*36 + ks*8 + t];
        qa[ks][1] = qbuf[r1*36 + ks*8 + t];
        qa[ks][2] = qbuf[r0*36 + ks*8 + t + 4];
        qa[ks][3] = qbuf[r1*36 + ks*8 + t + 4];
    }
    BARW();   // qbuf dead; P region may now be written

    auto stageK = [&](int s, int k0) {
        float* dst = myK + s * 64 * 36;
        #pragma unroll
        for (int i = 0; i < 4; i++) {
            int f = wtid + i * 128;
            int r = f >> 3, c4 = f & 7;
            cp16(dst + r * 36 + c4 * 4, g_k + (k0 + r) * 256 + hc + c4 * 4);
        }
        CP_COMMIT();
    };
    auto stageV = [&](int k0) {
        #pragma unroll
        for (int i = 0; i < 4; i++) {
            int f = wtid + i * 128;
            int r = f >> 3, c4 = f & 7;
            cp16(myV + r * 36 + c4 * 4, g_v + (k0 + r) * 256 + hc + c4 * 4);
        }
        CP_COMMIT();
    };

    float m0 = -INFINITY, m1 = -INFINITY, l0 = 0.f, l1 = 0.f;
    float O[4][4];
    #pragma unroll
    for (int nf = 0; nf < 4; nf++)
        #pragma unroll
        for (int r = 0; r < 4; r++) O[nf][r] = 0.f;

    int kbase = wg * 512;
    stageK(0, kbase);
    stageV(kbase);

    for (int ch = 0; ch < 8; ch++) {
        int s = ch & 1;
        int k0 = kbase + ch * 64;
        cp_wait<1>();          // K(ch) done (outstanding: [K(ch), V(ch)])
        BARW();
        if (ch < 7) stageK(s ^ 1, k0 + 64);

        float2 rb0[8], rb1[8];
        #pragma unroll
        for (int nf = 0; nf < 8; nf++) {
            rb0[nf] = *(const float2*)(relp0 + k0 + nf*8 + 2*t);
            rb1[nf] = *(const float2*)(relp1 + k0 + nf*8 + 2*t);
        }

        float S[8][4];
        #pragma unroll
        for (int nf = 0; nf < 8; nf++)
            #pragma unroll
            for (int r = 0; r < 4; r++) S[nf][r] = 0.f;
        float* Kc = myK + s * 64 * 36;
        #pragma unroll
        for (int ks = 0; ks < 4; ks++) {
            #pragma unroll
            for (int nf = 0; nf < 8; nf++) {
                unsigned b[2];
                int nr = nf * 8 + g;
                b[0] = __float_as_uint(Kc[nr*36 + ks*8 + t]);
                b[1] = __float_as_uint(Kc[nr*36 + ks*8 + t + 4]);
                mma_tf32(S[nf], qa[ks], b);
            }
        }

        #pragma unroll
        for (int nf = 0; nf < 8; nf++) {
            S[nf][0] += cf0 * rb0[nf].x;
            S[nf][1] += cf0 * rb0[nf].y;
            S[nf][2] += cf1 * rb1[nf].x;
            S[nf][3] += cf1 * rb1[nf].y;
        }

        float mx0 = -INFINITY, mx1 = -INFINITY;
        #pragma unroll
        for (int nf = 0; nf < 8; nf++) {
            mx0 = fmaxf(mx0, fmaxf(S[nf][0], S[nf][1]));
            mx1 = fmaxf(mx1, fmaxf(S[nf][2], S[nf][3]));
        }
        mx0 = fmaxf(mx0, __shfl_xor_sync(0xffffffffu, mx0, 1));
        mx0 = fmaxf(mx0, __shfl_xor_sync(0xffffffffu, mx0, 2));
        mx1 = fmaxf(mx1, __shfl_xor_sync(0xffffffffu, mx1, 1));
        mx1 = fmaxf(mx1, __shfl_xor_sync(0xffffffffu, mx1, 2));
        float mn0 = fmaxf(m0, mx0), mn1 = fmaxf(m1, mx1);
        float corr0 = __expf(m0 - mn0), corr1 = __expf(m1 - mn1);
        m0 = mn0; m1 = mn1;

        float ps0 = 0.f, ps1 = 0.f;
        #pragma unroll
        for (int nf = 0; nf < 8; nf++) {
            float p00 = __expf(S[nf][0] - mn0);
            float p01 = __expf(S[nf][1] - mn0);
            float p10 = __expf(S[nf][2] - mn1);
            float p11 = __expf(S[nf][3] - mn1);
            ps0 += p00 + p01; ps1 += p10 + p11;
            myP[r0*68 + nf*8 + 2*t]     = tf32r(p00);
            myP[r0*68 + nf*8 + 2*t + 1] = tf32r(p01);
            myP[r1*68 + nf*8 + 2*t]     = tf32r(p10);
            myP[r1*68 + nf*8 + 2*t + 1] = tf32r(p11);
        }
        ps0 += __shfl_xor_sync(0xffffffffu, ps0, 1);
        ps0 += __shfl_xor_sync(0xffffffffu, ps0, 2);
        ps1 += __shfl_xor_sync(0xffffffffu, ps1, 1);
        ps1 += __shfl_xor_sync(0xffffffffu, ps1, 2);
        l0 = l0 * corr0 + ps0;
        l1 = l1 * corr1 + ps1;
        #pragma unroll
        for (int nf = 0; nf < 4; nf++) {
            O[nf][0] *= corr0; O[nf][1] *= corr0;
            O[nf][2] *= corr1; O[nf][3] *= corr1;
        }
        __syncwarp();   // order myP STS before LDS (rows warp-private)

        if (ch < 7) cp_wait<1>(); else cp_wait<0>();   // V(ch) done
        BARW();

        #pragma unroll
        for (int ks = 0; ks < 8; ks++) {
            unsigned pa[4];
            pa[0] = myP[r0*68 + ks*8 + t];
            pa[1] = myP[r1*68 + ks*8 + t];
            pa[2] = myP[r0*68 + ks*8 + t + 4];
            pa[3] = myP[r1*68 + ks*8 + t + 4];
            #pragma unroll
            for (int nf = 0; nf < 4; nf++) {
                unsigned b[2];
                b[0] = __float_as_uint(myV[(ks*8 + t    )*36 + nf*8 + g]);
                b[1] = __float_as_uint(myV[(ks*8 + t + 4)*36 + nf*8 + g]);
                mma_tf32(O[nf], pa, b);
            }
        }
        BARW();                      // all wg threads done reading myV
        if (ch < 7) stageV(k0 + 64);
    }

    // ---- merge the two warpgroup partials ----
    __syncthreads();                 // both wgs finished; Ks region reusable
    float* Om = (float*)sm;          // [128][20]
    if (wg == 1) {
        float* o = Om + wtid * 20;
        #pragma unroll
        for (int nf = 0; nf < 4; nf++)
            #pragma unroll
            for (int j = 0; j < 4; j++) o[nf*4 + j] = O[nf][j];
        o[16] = m0; o[17] = l0; o[18] = m1; o[19] = l1;
    }
    __syncthreads();
    if (wg == 0) {
        float* o = Om + wtid * 20;
        float mB0 = o[16], lB0 = o[17], mB1 = o[18], lB1 = o[19];
        float M0 = fmaxf(m0, mB0), M1 = fmaxf(m1, mB1);
        float eA0 = __expf(m0 - M0), eB0 = __expf(mB0 - M0);
        float eA1 = __expf(m1 - M1), eB1 = __expf(mB1 - M1);
        float inv0 = 1.f / (l0 * eA0 + lB0 * eB0);
        float inv1 = 1.f / (l1 * eA1 + lB1 * eB1);
        #pragma unroll
        for (int nf = 0; nf < 4; nf++) {
            int col = hc + nf * 8 + 2 * t;
            float v0 = (O[nf][0] * eA0 + o[nf*4+0] * eB0) * inv0;
            float v1 = (O[nf][1] * eA0 + o[nf*4+1] * eB0) * inv0;
            float v2 = (O[nf][2] * eA1 + o[nf*4+2] * eB1) * inv1;
            float v3 = (O[nf][3] * eA1 + o[nf*4+3] * eB1) * inv1;
            *(float2*)(g_ctx + (q0 + r0) * 256 + col) = make_float2(v0, v1);
            *(float2*)(g_ctx + (q0 + r1) * 256 + col) = make_float2(v2, v3);
        }
    }
}

// ---- launch --------------------------------------------------------------
extern "C" void kernel_launch(void* const* d_in, const int* in_sizes, int n_in,
                              void* d_out, int out_size) {
    const float* V   = (const float*)d_in[0];
    const float* K   = (const float*)d_in[1];
    const float* Q   = (const float*)d_in[2];
    const float* pos = (const float*)d_in[3];
    const float* Wq  = (const float*)d_in[4];
    const float* Wk  = (const float*)d_in[5];
    const float* Wv  = (const float*)d_in[6];
    const float* Wr  = (const float*)d_in[7];
    const float* Wo  = (const float*)d_in[8];
    const float* bo  = (const float*)d_in[9];
    float* out = (float*)d_out;

    cudaFuncSetAttribute(attn_kernel,
                         cudaFuncAttributeMaxDynamicSharedMemorySize, 90624);

    prep_kernel<<<dim3(32, 4, 4), 128>>>(Q, K, V, Wq, Wk, Wv, pos);
    attn_kernel<<<dim3(16, 8), 256, 90624>>>(Wr);
    out_kernel<<<dim3(32, 4), 128>>>(Wo, bo, out);
}